// round 6
// baseline (speedup 1.0000x reference)
#include <cuda_runtime.h>
#include <math.h>

#define T_STEPS 256
#define B_SZ    256
#define I_SZ    512
#define H_SZ    512
#define G3      1536   // 3*H

typedef unsigned long long u64;

// ---------------- packed f32x2 helpers (Blackwell sm_103a) ------------------
__device__ __forceinline__ void ffma2(u64 &d, u64 a, u64 b) {
    asm("fma.rn.f32x2 %0, %1, %2, %0;" : "+l"(d) : "l"(a), "l"(b));
}
__device__ __forceinline__ u64 dup2(float x) {
    u64 r; asm("mov.b64 %0, {%1, %1};" : "=l"(r) : "f"(x)); return r;
}
__device__ __forceinline__ u64 pack2(float lo, float hi) {
    u64 r; asm("mov.b64 %0, {%1, %2};" : "=l"(r) : "f"(lo), "f"(hi)); return r;
}
__device__ __forceinline__ void unpack2(u64 v, float &lo, float &hi) {
    asm("mov.b64 {%0, %1}, %2;" : "=f"(lo), "=f"(hi) : "l"(v));
}
__device__ __forceinline__ float f2sum(u64 v) {
    float lo, hi; unpack2(v, lo, hi); return lo + hi;
}

// ---------------- fast transcendentals (MUFU tanh, sm_75+) ------------------
__device__ __forceinline__ float tanh_fast(float x) {
    float y; asm("tanh.approx.f32 %0, %1;" : "=f"(y) : "f"(x)); return y;
}
__device__ __forceinline__ float sigmoid_fast(float x) {
    return fmaf(tanh_fast(0.5f * x), 0.5f, 0.5f);
}

// ---------------- scratch (static device globals: allocation-free) ----------
static __device__ float g_gi[(size_t)T_STEPS * B_SZ * G3];   // (T,B,3H)
static __device__ unsigned g_count4[4] = {0, 0, 0, 0};
static __device__ volatile unsigned g_gen4[4] = {0, 0, 0, 0};

// ------- per-batch-group barrier (32 CTAs sharing one batch group) ----------
__device__ __forceinline__ void group_sync(int bg) {
    __syncthreads();
    if (threadIdx.x == 0) {
        unsigned gen = g_gen4[bg];
        __threadfence();                       // release prior writes
        if (atomicAdd(&g_count4[bg], 1u) == 31u) {
            g_count4[bg] = 0;
            __threadfence();
            g_gen4[bg] = gen + 1u;             // release
        } else {
            while (g_gen4[bg] == gen) { }      // spin (volatile load)
            __threadfence();                   // acquire
        }
    }
    __syncthreads();
}

// ============================================================================
// Kernel 1: gi = x @ W_ih^T + b_ih   (M=65536, N=1536, K=512) fp32 SGEMM
// 128x128x16 tiles, 256 threads, 8x8 microtile, FFMA2 packed along n,
// double-buffered SMEM (one __syncthreads per k-tile, LDG overlapped).
// ============================================================================
#define GM 128
#define GN 128
#define GK 16
#define NTILES (I_SZ / GK)   // 32

__global__ __launch_bounds__(256) void gi_gemm_kernel(
    const float* __restrict__ X,     // [M, 512]
    const float* __restrict__ W,     // [1536, 512]
    const float* __restrict__ bias)  // [1536]
{
    __shared__ float As[2][GK][GM];
    __shared__ float Bs[2][GK][GN];

    const int tid = threadIdx.x;
    const int m0 = blockIdx.x * GM;
    const int n0 = blockIdx.y * GN;
    const int tx = tid & 15;   // n direction
    const int ty = tid >> 4;   // m direction

    float4 ax[2], bx[2];
    const int r0_ = (tid)       >> 2, k40 = (tid)       & 3;
    const int r1_ = (tid + 256) >> 2, k41 = (tid + 256) & 3;

    u64 acc2[8][4];
    #pragma unroll
    for (int i = 0; i < 8; i++)
        #pragma unroll
        for (int j = 0; j < 4; j++) acc2[i][j] = 0ull;

    // ---- prologue: load + store tile 0 ----
    ax[0] = *(const float4*)(X + (size_t)(m0 + r0_) * I_SZ + k40 * 4);
    ax[1] = *(const float4*)(X + (size_t)(m0 + r1_) * I_SZ + k41 * 4);
    bx[0] = *(const float4*)(W + (size_t)(n0 + r0_) * I_SZ + k40 * 4);
    bx[1] = *(const float4*)(W + (size_t)(n0 + r1_) * I_SZ + k41 * 4);
    As[0][k40 * 4 + 0][r0_] = ax[0].x; As[0][k40 * 4 + 1][r0_] = ax[0].y;
    As[0][k40 * 4 + 2][r0_] = ax[0].z; As[0][k40 * 4 + 3][r0_] = ax[0].w;
    As[0][k41 * 4 + 0][r1_] = ax[1].x; As[0][k41 * 4 + 1][r1_] = ax[1].y;
    As[0][k41 * 4 + 2][r1_] = ax[1].z; As[0][k41 * 4 + 3][r1_] = ax[1].w;
    Bs[0][k40 * 4 + 0][r0_] = bx[0].x; Bs[0][k40 * 4 + 1][r0_] = bx[0].y;
    Bs[0][k40 * 4 + 2][r0_] = bx[0].z; Bs[0][k40 * 4 + 3][r0_] = bx[0].w;
    Bs[0][k41 * 4 + 0][r1_] = bx[1].x; Bs[0][k41 * 4 + 1][r1_] = bx[1].y;
    Bs[0][k41 * 4 + 2][r1_] = bx[1].z; Bs[0][k41 * 4 + 3][r1_] = bx[1].w;
    __syncthreads();

    for (int t = 0; t < NTILES; ++t) {
        const int cb = t & 1;
        if (t + 1 < NTILES) {
            const int kt = (t + 1) * GK;
            ax[0] = *(const float4*)(X + (size_t)(m0 + r0_) * I_SZ + kt + k40 * 4);
            ax[1] = *(const float4*)(X + (size_t)(m0 + r1_) * I_SZ + kt + k41 * 4);
            bx[0] = *(const float4*)(W + (size_t)(n0 + r0_) * I_SZ + kt + k40 * 4);
            bx[1] = *(const float4*)(W + (size_t)(n0 + r1_) * I_SZ + kt + k41 * 4);
        }

        #pragma unroll
        for (int k = 0; k < GK; k++) {
            float a_[8];
            *(float4*)&a_[0] = *(const float4*)&As[cb][k][ty * 8];
            *(float4*)&a_[4] = *(const float4*)&As[cb][k][ty * 8 + 4];
            float4 bv0 = *(const float4*)&Bs[cb][k][tx * 8];
            float4 bv1 = *(const float4*)&Bs[cb][k][tx * 8 + 4];
            u64 b2[4];
            b2[0] = pack2(bv0.x, bv0.y);
            b2[1] = pack2(bv0.z, bv0.w);
            b2[2] = pack2(bv1.x, bv1.y);
            b2[3] = pack2(bv1.z, bv1.w);
            #pragma unroll
            for (int i = 0; i < 8; i++) {
                u64 ad = dup2(a_[i]);
                #pragma unroll
                for (int j = 0; j < 4; j++) ffma2(acc2[i][j], ad, b2[j]);
            }
        }

        if (t + 1 < NTILES) {
            const int nb = cb ^ 1;
            As[nb][k40 * 4 + 0][r0_] = ax[0].x; As[nb][k40 * 4 + 1][r0_] = ax[0].y;
            As[nb][k40 * 4 + 2][r0_] = ax[0].z; As[nb][k40 * 4 + 3][r0_] = ax[0].w;
            As[nb][k41 * 4 + 0][r1_] = ax[1].x; As[nb][k41 * 4 + 1][r1_] = ax[1].y;
            As[nb][k41 * 4 + 2][r1_] = ax[1].z; As[nb][k41 * 4 + 3][r1_] = ax[1].w;
            Bs[nb][k40 * 4 + 0][r0_] = bx[0].x; Bs[nb][k40 * 4 + 1][r0_] = bx[0].y;
            Bs[nb][k40 * 4 + 2][r0_] = bx[0].z; Bs[nb][k40 * 4 + 3][r0_] = bx[0].w;
            Bs[nb][k41 * 4 + 0][r1_] = bx[1].x; Bs[nb][k41 * 4 + 1][r1_] = bx[1].y;
            Bs[nb][k41 * 4 + 2][r1_] = bx[1].z; Bs[nb][k41 * 4 + 3][r1_] = bx[1].w;
        }
        __syncthreads();
    }

    const int m_base = m0 + ty * 8;
    const int n_base = n0 + tx * 8;
    float bb[8];
    #pragma unroll
    for (int j = 0; j < 8; j++) bb[j] = bias[n_base + j];

    #pragma unroll
    for (int i = 0; i < 8; i++) {
        float c[8];
        #pragma unroll
        for (int j = 0; j < 4; j++) unpack2(acc2[i][j], c[2 * j], c[2 * j + 1]);
        float4 v0, v1;
        v0.x = c[0] + bb[0]; v0.y = c[1] + bb[1];
        v0.z = c[2] + bb[2]; v0.w = c[3] + bb[3];
        v1.x = c[4] + bb[4]; v1.y = c[5] + bb[5];
        v1.z = c[6] + bb[6]; v1.w = c[7] + bb[7];
        float* crow = g_gi + (size_t)(m_base + i) * G3 + n_base;
        *(float4*)(crow)     = v0;
        *(float4*)(crow + 4) = v1;
    }
}

// ============================================================================
// Kernel 2: persistent GRU recurrence.
// Grid = 128 CTAs = 4 batch-groups (64 b) x 32 col-groups (16 j).
// - W_hh slice (3 x 16 x 512) SMEM-resident for all 256 steps.
// - 4 independent 32-CTA barriers (one per batch group).
// - NO separate hidden buffer: out[t] IS h_{t+1}; step t stages from out[t-1]
//   (h0 at t=0).
// - h staging split in k: phase A (k<256) staged then synced; phase B
//   (k>=256) register-pipelined UNDER the FMA-A loop (disjoint SMEM region).
// - Epilogue: h_new restaged into sH, then coalesced STG.128 to out[t]
//   (64B row-chunks, dense sectors) instead of scattered 4B stores.
// - FFMA2 packed along k, LDS.128 operand feeds (SH_STRIDE=516).
// ============================================================================
#define R_NCTA    128
#define R_THREADS 128
#define RB        64
#define RJ        16
#define SH_STRIDE 516           // multiple of 4 -> 16B-aligned rows

#define SW_FLOATS (3 * RJ * SH_STRIDE)              // 24768
#define SH_FLOATS (RB * SH_STRIDE)                  // 33024
#define R_SMEM_BYTES ((SW_FLOATS + SH_FLOATS) * 4)  // 231168 B

extern __shared__ float r_smem[];

// FMA over k in [kbeg,kend): 24 packed accumulators, LDS.128 feeds.
__device__ __forceinline__ void fma_span(
    int kbeg, int kend,
    const float* wR0, const float* wR1, const float* wZ0, const float* wZ1,
    const float* wN0, const float* wN1,
    const float* hr0, const float* hr1, const float* hr2, const float* hr3,
    u64 accR[4][2], u64 accZ[4][2], u64 accN[4][2])
{
    #pragma unroll 2
    for (int k = kbeg; k < kend; k += 4) {
        float4 w0q = *(const float4*)(wR0 + k);
        float4 w1q = *(const float4*)(wR1 + k);
        float4 w2q = *(const float4*)(wZ0 + k);
        float4 w3q = *(const float4*)(wZ1 + k);
        float4 w4q = *(const float4*)(wN0 + k);
        float4 w5q = *(const float4*)(wN1 + k);
        float4 h0q = *(const float4*)(hr0 + k);
        float4 h1q = *(const float4*)(hr1 + k);
        float4 h2q = *(const float4*)(hr2 + k);
        float4 h3q = *(const float4*)(hr3 + k);

        u64 w0a = pack2(w0q.x, w0q.y), w0b = pack2(w0q.z, w0q.w);
        u64 w1a = pack2(w1q.x, w1q.y), w1b = pack2(w1q.z, w1q.w);
        u64 w2a = pack2(w2q.x, w2q.y), w2b = pack2(w2q.z, w2q.w);
        u64 w3a = pack2(w3q.x, w3q.y), w3b = pack2(w3q.z, w3q.w);
        u64 w4a = pack2(w4q.x, w4q.y), w4b = pack2(w4q.z, w4q.w);
        u64 w5a = pack2(w5q.x, w5q.y), w5b = pack2(w5q.z, w5q.w);
        u64 h0a = pack2(h0q.x, h0q.y), h0b = pack2(h0q.z, h0q.w);
        u64 h1a = pack2(h1q.x, h1q.y), h1b = pack2(h1q.z, h1q.w);
        u64 h2a = pack2(h2q.x, h2q.y), h2b = pack2(h2q.z, h2q.w);
        u64 h3a = pack2(h3q.x, h3q.y), h3b = pack2(h3q.z, h3q.w);

        ffma2(accR[0][0], h0a, w0a); ffma2(accR[0][1], h0a, w1a);
        ffma2(accZ[0][0], h0a, w2a); ffma2(accZ[0][1], h0a, w3a);
        ffma2(accN[0][0], h0a, w4a); ffma2(accN[0][1], h0a, w5a);
        ffma2(accR[1][0], h1a, w0a); ffma2(accR[1][1], h1a, w1a);
        ffma2(accZ[1][0], h1a, w2a); ffma2(accZ[1][1], h1a, w3a);
        ffma2(accN[1][0], h1a, w4a); ffma2(accN[1][1], h1a, w5a);
        ffma2(accR[2][0], h2a, w0a); ffma2(accR[2][1], h2a, w1a);
        ffma2(accZ[2][0], h2a, w2a); ffma2(accZ[2][1], h2a, w3a);
        ffma2(accN[2][0], h2a, w4a); ffma2(accN[2][1], h2a, w5a);
        ffma2(accR[3][0], h3a, w0a); ffma2(accR[3][1], h3a, w1a);
        ffma2(accZ[3][0], h3a, w2a); ffma2(accZ[3][1], h3a, w3a);
        ffma2(accN[3][0], h3a, w4a); ffma2(accN[3][1], h3a, w5a);

        ffma2(accR[0][0], h0b, w0b); ffma2(accR[0][1], h0b, w1b);
        ffma2(accZ[0][0], h0b, w2b); ffma2(accZ[0][1], h0b, w3b);
        ffma2(accN[0][0], h0b, w4b); ffma2(accN[0][1], h0b, w5b);
        ffma2(accR[1][0], h1b, w0b); ffma2(accR[1][1], h1b, w1b);
        ffma2(accZ[1][0], h1b, w2b); ffma2(accZ[1][1], h1b, w3b);
        ffma2(accN[1][0], h1b, w4b); ffma2(accN[1][1], h1b, w5b);
        ffma2(accR[2][0], h2b, w0b); ffma2(accR[2][1], h2b, w1b);
        ffma2(accZ[2][0], h2b, w2b); ffma2(accZ[2][1], h2b, w3b);
        ffma2(accN[2][0], h2b, w4b); ffma2(accN[2][1], h2b, w5b);
        ffma2(accR[3][0], h3b, w0b); ffma2(accR[3][1], h3b, w1b);
        ffma2(accZ[3][0], h3b, w2b); ffma2(accZ[3][1], h3b, w3b);
        ffma2(accN[3][0], h3b, w4b); ffma2(accN[3][1], h3b, w5b);
    }
}

__global__ __launch_bounds__(R_THREADS, 1) void gru_recurrence_kernel(
    const float* __restrict__ h0,     // [B, H]
    const float* __restrict__ masks,  // [T, B]
    const float* __restrict__ W_hh,   // [3H, H]
    const float* __restrict__ b_hh,   // [3H]
    float* __restrict__ out)          // y raw at [0, T*B*H), hT at tail
{
    float* sW = r_smem;                // [3*RJ][SH_STRIDE]
    float* sH = r_smem + SW_FLOATS;    // [RB][SH_STRIDE]

    const int tid = threadIdx.x;
    const int bid = blockIdx.x;
    const int bg = bid >> 5;           // 0..3
    const int cg = bid & 31;           // 0..31
    const int b0 = bg * RB;
    const int j0 = cg * RJ;

    // ---- load W_hh slice into SMEM once ----
    for (int i = tid; i < 3 * RJ * (H_SZ / 4); i += R_THREADS) {
        int k4  = i & 127;
        int row = i >> 7;              // 0..47 : g*RJ + jj
        int g = row / RJ, jj = row - g * RJ;
        float4 v = *(const float4*)(W_hh + (size_t)(g * H_SZ + j0 + jj) * H_SZ + k4 * 4);
        *(float4*)(sW + row * SH_STRIDE + k4 * 4) = v;
    }
    __syncthreads();

    // thread tile: 4 batches x 2 j-cols x 3 gates = 24 accumulators
    const int bt = tid & 15;   // b = b0 + bt + 16*i
    const int jt = tid >> 4;   // 0..7 ; j = j0 + jt*2 + jj

    const float* wR0 = sW + (0 * RJ + jt * 2 + 0) * SH_STRIDE;
    const float* wR1 = sW + (0 * RJ + jt * 2 + 1) * SH_STRIDE;
    const float* wZ0 = sW + (1 * RJ + jt * 2 + 0) * SH_STRIDE;
    const float* wZ1 = sW + (1 * RJ + jt * 2 + 1) * SH_STRIDE;
    const float* wN0 = sW + (2 * RJ + jt * 2 + 0) * SH_STRIDE;
    const float* wN1 = sW + (2 * RJ + jt * 2 + 1) * SH_STRIDE;

    const float* hr0 = sH + (bt + 0)  * SH_STRIDE;
    const float* hr1 = sH + (bt + 16) * SH_STRIDE;
    const float* hr2 = sH + (bt + 32) * SH_STRIDE;
    const float* hr3 = sH + (bt + 48) * SH_STRIDE;

    // loop-invariant biases (jj = 0,1)
    float bhr_[2], bhz_[2], bhn_[2];
    #pragma unroll
    for (int jj = 0; jj < 2; jj++) {
        const int j = j0 + jt * 2 + jj;
        bhr_[jj] = b_hh[j];
        bhz_[jj] = b_hh[H_SZ + j];
        bhn_[jj] = b_hh[2 * H_SZ + j];
    }

    for (int t = 0; t < T_STEPS; ++t) {
        // staging source: h0 at t=0, else previous out block (= h_t)
        const float* hsrc = (t == 0)
            ? (h0 + (size_t)b0 * H_SZ)
            : (out + ((size_t)(t - 1) * B_SZ + b0) * H_SZ);
        const float4* hsrc4 = (const float4*)hsrc;
        const float* mrow = masks + (size_t)t * B_SZ + b0;

        // ---- phase A: stage k in [0,256) ----
        for (int i = tid; i < RB * 64; i += R_THREADS) {
            int b  = i >> 6;
            int k4 = i & 63;
            float m = mrow[b];
            float4 v = hsrc4[b * (H_SZ / 4) + k4];
            float4 s;
            s.x = v.x * m; s.y = v.y * m; s.z = v.z * m; s.w = v.w * m;
            *(float4*)(sH + b * SH_STRIDE + k4 * 4) = s;
        }
        __syncthreads();

        // ---- prefetch gi operands (DRAM) -> land under FMA-A ----
        float gir[2][4], giz[2][4], gin[2][4];
        #pragma unroll
        for (int jj = 0; jj < 2; jj++) {
            const int j = j0 + jt * 2 + jj;
            #pragma unroll
            for (int i = 0; i < 4; i++) {
                const int b = b0 + bt + 16 * i;
                const float* gbase = g_gi + ((size_t)t * B_SZ + b) * G3 + j;
                gir[jj][i] = __ldg(gbase);
                giz[jj][i] = __ldg(gbase + H_SZ);
                gin[jj][i] = __ldg(gbase + 2 * H_SZ);
            }
        }

        u64 accR[4][2], accZ[4][2], accN[4][2];
        #pragma unroll
        for (int i = 0; i < 4; i++) {
            accR[i][0] = accR[i][1] = 0ull;
            accZ[i][0] = accZ[i][1] = 0ull;
            accN[i][0] = accN[i][1] = 0ull;
        }

        // ---- FMA-A over k [0,256) with phase-B staging pipelined under it.
        // Phase B: b = i>>6, k4 = 64 + (i&63); writes sH k>=256 (disjoint).
        #pragma unroll
        for (int grp = 0; grp < 8; grp++) {
            float4 st[4];
            float  mk[4];
            #pragma unroll
            for (int n = 0; n < 4; n++) {
                int i = grp * 512 + n * R_THREADS + tid;
                int b  = i >> 6;
                int k4 = 64 + (i & 63);
                mk[n] = mrow[b];
                st[n] = hsrc4[b * (H_SZ / 4) + k4];
            }
            fma_span(grp * 32, grp * 32 + 32,
                     wR0, wR1, wZ0, wZ1, wN0, wN1,
                     hr0, hr1, hr2, hr3, accR, accZ, accN);
            #pragma unroll
            for (int n = 0; n < 4; n++) {
                int i = grp * 512 + n * R_THREADS + tid;
                int b  = i >> 6;
                int k4 = 64 + (i & 63);
                float4 s;
                s.x = st[n].x * mk[n]; s.y = st[n].y * mk[n];
                s.z = st[n].z * mk[n]; s.w = st[n].w * mk[n];
                *(float4*)(sH + b * SH_STRIDE + k4 * 4) = s;
            }
        }
        __syncthreads();

        // ---- FMA-B over k [256,512) ----
        fma_span(256, 512,
                 wR0, wR1, wZ0, wZ1, wN0, wN1,
                 hr0, hr1, hr2, hr3, accR, accZ, accN);

        // ---- gates: compute h_new into registers (reads hm from sH) ----
        float hnew[2][4];
        #pragma unroll
        for (int jj = 0; jj < 2; jj++) {
            const int j = j0 + jt * 2 + jj;
            #pragma unroll
            for (int i = 0; i < 4; i++) {
                float r = sigmoid_fast(gir[jj][i] + f2sum(accR[i][jj]) + bhr_[jj]);
                float z = sigmoid_fast(giz[jj][i] + f2sum(accZ[i][jj]) + bhz_[jj]);
                float n = tanh_fast(gin[jj][i] + r * (f2sum(accN[i][jj]) + bhn_[jj]));
                float hm = sH[(bt + 16 * i) * SH_STRIDE + j];
                hnew[jj][i] = (1.0f - z) * n + z * hm;
            }
        }
        __syncthreads();   // all sH reads (FMA-B + hm) done before overwrite

        // ---- restage h_new into sH (scattered STS, crossbar-local) ----
        #pragma unroll
        for (int jj = 0; jj < 2; jj++) {
            const int j = j0 + jt * 2 + jj;
            #pragma unroll
            for (int i = 0; i < 4; i++)
                sH[(bt + 16 * i) * SH_STRIDE + j] = hnew[jj][i];
        }
        __syncthreads();

        // ---- coalesced write-out of the 64 x 16 slice (STG.128) ----
        {
            float* dst = out + ((size_t)t * B_SZ + b0) * H_SZ + j0;
            #pragma unroll
            for (int rep = 0; rep < 2; rep++) {
                int l = tid + rep * R_THREADS;     // 0..255
                int row = l >> 2;                  // 0..63
                int c   = l & 3;                   // 0..3
                float4 v = *(const float4*)(sH + row * SH_STRIDE + j0 + c * 4);
                *(float4*)(dst + (size_t)row * H_SZ + c * 4) = v;
            }
            if (t == T_STEPS - 1) {
                float* tail = out + (size_t)T_STEPS * B_SZ * H_SZ
                                  + (size_t)b0 * H_SZ + j0;
                #pragma unroll
                for (int rep = 0; rep < 2; rep++) {
                    int l = tid + rep * R_THREADS;
                    int row = l >> 2;
                    int c   = l & 3;
                    float4 v = *(const float4*)(sH + row * SH_STRIDE + j0 + c * 4);
                    *(float4*)(tail + (size_t)row * H_SZ + c * 4) = v;
                }
            }
        }

        group_sync(bg);   // out[t] for this batch group visible before restaging
    }
}

// ============================================================================
// Kernel 3: in-place LayerNorm over the y region. One 128-thread CTA per row.
// ============================================================================
__global__ __launch_bounds__(128) void layernorm_kernel(
    float* __restrict__ y,            // [T*B, 512] in-place
    const float* __restrict__ w,      // [512]
    const float* __restrict__ b)      // [512]
{
    __shared__ float ss[4], sq[4];
    const size_t row = blockIdx.x;
    float* xr = y + row * H_SZ;
    const int tid = threadIdx.x;

    float4 v = ((const float4*)xr)[tid];
    float s = v.x + v.y + v.z + v.w;
    float q = v.x * v.x + v.y * v.y + v.z * v.z + v.w * v.w;
    #pragma unroll
    for (int o = 16; o > 0; o >>= 1) {
        s += __shfl_xor_sync(0xffffffffu, s, o);
        q += __shfl_xor_sync(0xffffffffu, q, o);
    }
    if ((tid & 31) == 0) { ss[tid >> 5] = s; sq[tid >> 5] = q; }
    __syncthreads();
    s = ss[0] + ss[1] + ss[2] + ss[3];
    q = sq[0] + sq[1] + sq[2] + sq[3];

    const float mu  = s * (1.0f / (float)H_SZ);
    const float var = q * (1.0f / (float)H_SZ) - mu * mu;
    const float inv = rsqrtf(var + 1e-5f);

    float4 wv = ((const float4*)w)[tid];
    float4 bv = ((const float4*)b)[tid];
    float4 o;
    o.x = (v.x - mu) * inv * wv.x + bv.x;
    o.y = (v.y - mu) * inv * wv.y + bv.y;
    o.z = (v.z - mu) * inv * wv.z + bv.z;
    o.w = (v.w - mu) * inv * wv.w + bv.w;
    ((float4*)xr)[tid] = o;
}

// ============================================================================
// kernel_launch
// ============================================================================
extern "C" void kernel_launch(void* const* d_in, const int* in_sizes, int n_in,
                              void* d_out, int out_size) {
    const float* x     = (const float*)d_in[0];  // (T,B,I)
    const float* h0    = (const float*)d_in[1];  // (1,B,H)
    const float* masks = (const float*)d_in[2];  // (T,B,1)
    const float* W_ih  = (const float*)d_in[3];  // (3H,I)
    const float* W_hh  = (const float*)d_in[4];  // (3H,H)
    const float* b_ih  = (const float*)d_in[5];  // (3H)
    const float* b_hh  = (const float*)d_in[6];  // (3H)
    const float* ln_w  = (const float*)d_in[7];  // (H)
    const float* ln_b  = (const float*)d_in[8];  // (H)
    float* out = (float*)d_out;

    // 1) input projections gi = x @ W_ih^T + b_ih
    dim3 ggrid((T_STEPS * B_SZ) / GM, G3 / GN);  // (512, 12)
    gi_gemm_kernel<<<ggrid, 256>>>(x, W_ih, b_ih);

    // 2) persistent recurrence (W_hh slice SMEM-resident; 231,168 B dynamic)
    cudaFuncSetAttribute(gru_recurrence_kernel,
                         cudaFuncAttributeMaxDynamicSharedMemorySize, R_SMEM_BYTES);
    gru_recurrence_kernel<<<R_NCTA, R_THREADS, R_SMEM_BYTES>>>(h0, masks, W_hh, b_hh, out);

    // 3) in-place LayerNorm on y region (hT tail untouched)
    layernorm_kernel<<<T_STEPS * B_SZ, 128>>>(out, ln_w, ln_b);
}